// round 1
// baseline (speedup 1.0000x reference)
#include <cuda_runtime.h>

// BoundaryAwareBCELoss: fused 3x3 binary morphology boundary + weighted BCE mean.
// pred:   (32,1,1024,1024) fp32 in (0,1)
// target: (32,1,1024,1024) fp32 binary {0,1}
// out:    scalar fp32 = mean( w * bce ), w = 3 if 3x3 window of target is
//         non-uniform (dilate != erode), else 1; bce = -log(t ? p : 1-p).

#define IMG_W 1024
#define IMG_H 1024
#define IMG_B 32
#define NPIX  ((long long)IMG_B * IMG_H * IMG_W)

__device__ double g_acc;

__global__ void babce_zero_kernel() { g_acc = 0.0; }

__global__ __launch_bounds__(256) void babce_main_kernel(
    const float* __restrict__ pred, const float* __restrict__ target)
{
    __shared__ float s_cmax[IMG_W];
    __shared__ float s_cmin[IMG_W];
    __shared__ float s_warp[8];

    const int y   = blockIdx.x;       // row
    const int b   = blockIdx.y;       // batch image
    const int tid = threadIdx.x;      // 256 threads, 4 cols each
    const int x0  = tid * 4;

    const size_t img = (size_t)b * (size_t)IMG_H * IMG_W;
    const int yu = (y > 0)        ? y - 1 : y;       // clamp == excluding pad
    const int yd = (y < IMG_H - 1) ? y + 1 : y;      // (binary min/max neutral)

    const float4 tm = *(const float4*)(target + img + (size_t)y  * IMG_W + x0);
    const float4 tu = *(const float4*)(target + img + (size_t)yu * IMG_W + x0);
    const float4 td = *(const float4*)(target + img + (size_t)yd * IMG_W + x0);
    const float4 pp = *(const float4*)(pred   + img + (size_t)y  * IMG_W + x0);

    // vertical (column-wise) min/max of the 3 rows
    float4 cmx, cmn;
    cmx.x = fmaxf(tm.x, fmaxf(tu.x, td.x));  cmn.x = fminf(tm.x, fminf(tu.x, td.x));
    cmx.y = fmaxf(tm.y, fmaxf(tu.y, td.y));  cmn.y = fminf(tm.y, fminf(tu.y, td.y));
    cmx.z = fmaxf(tm.z, fmaxf(tu.z, td.z));  cmn.z = fminf(tm.z, fminf(tu.z, td.z));
    cmx.w = fmaxf(tm.w, fmaxf(tu.w, td.w));  cmn.w = fminf(tm.w, fminf(tu.w, td.w));

    *(float4*)(s_cmax + x0) = cmx;
    *(float4*)(s_cmin + x0) = cmn;
    __syncthreads();

    const float t4[4] = { tm.x, tm.y, tm.z, tm.w };
    const float p4[4] = { pp.x, pp.y, pp.z, pp.w };

    float sum = 0.0f;
    #pragma unroll
    for (int i = 0; i < 4; i++) {
        const int x  = x0 + i;
        const int xl = (x > 0)         ? x - 1 : x;
        const int xr = (x < IMG_W - 1) ? x + 1 : x;
        const float bmax = fmaxf(s_cmax[x], fmaxf(s_cmax[xl], s_cmax[xr]));
        const float bmin = fminf(s_cmin[x], fminf(s_cmin[xl], s_cmin[xr]));
        const float t = t4[i];
        const float p = p4[i];
        const float arg = (t > 0.5f) ? p : (1.0f - p);
        const float bce = -__logf(arg);
        const float w   = (bmax != bmin) ? 3.0f : 1.0f;
        sum = fmaf(w, bce, sum);
    }

    // warp reduce
    #pragma unroll
    for (int off = 16; off > 0; off >>= 1)
        sum += __shfl_xor_sync(0xFFFFFFFFu, sum, off);

    const int lane = tid & 31;
    const int wid  = tid >> 5;
    if (lane == 0) s_warp[wid] = sum;
    __syncthreads();

    if (wid == 0) {
        float v = (lane < 8) ? s_warp[lane] : 0.0f;
        #pragma unroll
        for (int off = 4; off > 0; off >>= 1)
            v += __shfl_xor_sync(0xFFFFFFFFu, v, off);
        if (lane == 0)
            atomicAdd(&g_acc, (double)v);
    }
}

__global__ void babce_final_kernel(float* __restrict__ out) {
    out[0] = (float)(g_acc / (double)NPIX);
}

extern "C" void kernel_launch(void* const* d_in, const int* in_sizes, int n_in,
                              void* d_out, int out_size)
{
    const float* pred   = (const float*)d_in[0];
    const float* target = (const float*)d_in[1];
    float* out = (float*)d_out;

    babce_zero_kernel<<<1, 1>>>();
    dim3 grid(IMG_H, IMG_B);
    babce_main_kernel<<<grid, 256>>>(pred, target);
    babce_final_kernel<<<1, 1>>>(out);
}

// round 2
// speedup vs baseline: 1.1270x; 1.1270x over previous
#include <cuda_runtime.h>

// BoundaryAwareBCELoss: fused 3x3 binary morphology boundary + weighted BCE mean.
// pred:   (32,1,1024,1024) fp32 in (0,1)
// target: (32,1,1024,1024) fp32 binary {0,1}
// out[0]: mean( w * bce ), w = 3 if 3x3 target window non-uniform else 1,
//         bce = -log(t ? p : 1-p).
//
// R2: 16-row strips per block, register-rolling vertical window (1 target +
// 1 pred load per pixel), double-buffered shared column-min/max (1 bar/row),
// deterministic partial-sum array instead of zero-kernel + atomics.

#define IMG_W 1024
#define IMG_H 1024
#define IMG_B 32
#define RPB   16                                   // rows per block
#define NBLK  ((IMG_H / RPB) * IMG_B)              // 2048 partials
#define NPIXD ((double)IMG_B * IMG_H * IMG_W)

__device__ float g_partial[NBLK];

__global__ __launch_bounds__(256) void babce_main_kernel(
    const float* __restrict__ pred, const float* __restrict__ target)
{
    __shared__ float s_cmax[2][IMG_W];
    __shared__ float s_cmin[2][IMG_W];
    __shared__ float s_warp[8];

    const int tid = threadIdx.x;          // 256 threads, float4 = 4 cols each
    const int x0  = tid * 4;
    const int y0  = blockIdx.x * RPB;
    const int b   = blockIdx.y;

    const float* __restrict__ timg = target + (size_t)b * IMG_H * IMG_W;
    const float* __restrict__ pimg = pred   + (size_t)b * IMG_H * IMG_W;

    // rolling vertical window registers (clamped top halo)
    const int yu = (y0 > 0) ? y0 - 1 : 0;
    float4 tu = *(const float4*)(timg + (size_t)yu * IMG_W + x0);
    float4 tm = *(const float4*)(timg + (size_t)y0 * IMG_W + x0);

    float sum = 0.0f;

    #pragma unroll 2
    for (int r = 0; r < RPB; r++) {
        const int y  = y0 + r;
        const int yd = (y < IMG_H - 1) ? y + 1 : y;   // clamped bottom halo
        const float4 td = *(const float4*)(timg + (size_t)yd * IMG_W + x0);
        const float4 pp = *(const float4*)(pimg + (size_t)y  * IMG_W + x0);

        // vertical (column) min/max of rows y-1, y, y+1
        float4 cmx, cmn;
        cmx.x = fmaxf(tm.x, fmaxf(tu.x, td.x));  cmn.x = fminf(tm.x, fminf(tu.x, td.x));
        cmx.y = fmaxf(tm.y, fmaxf(tu.y, td.y));  cmn.y = fminf(tm.y, fminf(tu.y, td.y));
        cmx.z = fmaxf(tm.z, fmaxf(tu.z, td.z));  cmn.z = fminf(tm.z, fminf(tu.z, td.z));
        cmx.w = fmaxf(tm.w, fmaxf(tu.w, td.w));  cmn.w = fminf(tm.w, fminf(tu.w, td.w));

        const int buf = r & 1;
        *(float4*)(&s_cmax[buf][x0]) = cmx;
        *(float4*)(&s_cmin[buf][x0]) = cmn;
        __syncthreads();   // single barrier: double buffer makes next-iter
                           // writes land in the other buffer

        const float t4[4] = { tm.x, tm.y, tm.z, tm.w };
        const float p4[4] = { pp.x, pp.y, pp.z, pp.w };

        #pragma unroll
        for (int i = 0; i < 4; i++) {
            const int x  = x0 + i;
            const int xl = (x > 0)         ? x - 1 : x;
            const int xr = (x < IMG_W - 1) ? x + 1 : x;
            const float bmax = fmaxf(s_cmax[buf][x], fmaxf(s_cmax[buf][xl], s_cmax[buf][xr]));
            const float bmin = fminf(s_cmin[buf][x], fminf(s_cmin[buf][xl], s_cmin[buf][xr]));
            const float arg  = (t4[i] > 0.5f) ? p4[i] : (1.0f - p4[i]);
            const float bce  = -__logf(arg);
            const float w    = (bmax != bmin) ? 3.0f : 1.0f;
            sum = fmaf(w, bce, sum);
        }

        tu = tm;  tm = td;
    }

    // block reduction
    #pragma unroll
    for (int off = 16; off > 0; off >>= 1)
        sum += __shfl_xor_sync(0xFFFFFFFFu, sum, off);

    const int lane = tid & 31;
    const int wid  = tid >> 5;
    if (lane == 0) s_warp[wid] = sum;
    __syncthreads();

    if (wid == 0) {
        float v = (lane < 8) ? s_warp[lane] : 0.0f;
        #pragma unroll
        for (int off = 4; off > 0; off >>= 1)
            v += __shfl_xor_sync(0xFFFFFFFFu, v, off);
        if (lane == 0)
            g_partial[blockIdx.y * gridDim.x + blockIdx.x] = v;
    }
}

__global__ __launch_bounds__(1024) void babce_final_kernel(float* __restrict__ out)
{
    __shared__ double s_warp[32];
    const int tid = threadIdx.x;

    double v = (double)g_partial[tid] + (double)g_partial[tid + 1024];

    #pragma unroll
    for (int off = 16; off > 0; off >>= 1)
        v += __shfl_xor_sync(0xFFFFFFFFu, v, off);

    const int lane = tid & 31;
    const int wid  = tid >> 5;
    if (lane == 0) s_warp[wid] = v;
    __syncthreads();

    if (wid == 0) {
        double t = (lane < 32) ? s_warp[lane] : 0.0;
        #pragma unroll
        for (int off = 16; off > 0; off >>= 1)
            t += __shfl_xor_sync(0xFFFFFFFFu, t, off);
        if (lane == 0)
            out[0] = (float)(t / NPIXD);
    }
}

extern "C" void kernel_launch(void* const* d_in, const int* in_sizes, int n_in,
                              void* d_out, int out_size)
{
    const float* pred   = (const float*)d_in[0];
    const float* target = (const float*)d_in[1];
    float* out = (float*)d_out;

    dim3 grid(IMG_H / RPB, IMG_B);   // (64, 32) = 2048 blocks
    babce_main_kernel<<<grid, 256>>>(pred, target);
    babce_final_kernel<<<1, 1024>>>(out);
}

// round 4
// speedup vs baseline: 1.3088x; 1.1614x over previous
#include <cuda_runtime.h>

// BoundaryAwareBCELoss — fused 3x3 binary morphology boundary + weighted BCE mean.
// R3 (resubmit after infra failure; kernel never ran): warp-private 128-col
// segments, shuffle-based horizontal combine with rolling halo registers
// (no shared mem, no per-row barriers), fused final reduction via
// threadfence pattern (single kernel launch).

#define IMG_W 1024
#define IMG_H 1024
#define IMG_B 32
#define RPB   32
#define GX    (IMG_H / RPB)          // 32
#define NBLK  (GX * IMG_B)           // 1024
#define NPIXD ((double)IMG_B * IMG_H * IMG_W)

__device__ float g_partial[NBLK];
__device__ unsigned int g_count;     // zero at module load; reset each call

__global__ __launch_bounds__(256) void babce_kernel(
    const float* __restrict__ pred, const float* __restrict__ target,
    float* __restrict__ out)
{
    __shared__ float  s_warp[8];
    __shared__ double s_dwarp[8];
    __shared__ bool   s_last;

    const int tid  = threadIdx.x;
    const int lane = tid & 31;
    const int wid  = tid >> 5;
    const int y0   = blockIdx.x * RPB;
    const int b    = blockIdx.y;

    const int c0 = wid * 128;                 // warp column base
    const int x0 = c0 + lane * 4;             // this thread's 4 columns
    const bool is_edge = (lane == 0) || (lane == 31);
    // halo column this lane tracks (clamped => min/max-neutral == SAME pad)
    const int hcol = (lane == 0) ? ((c0 > 0) ? c0 - 1 : 0)
                                 : ((c0 + 128 < IMG_W) ? c0 + 128 : IMG_W - 1);

    const float* __restrict__ timg = target + (size_t)b * IMG_H * IMG_W;
    const float* __restrict__ pimg = pred   + (size_t)b * IMG_H * IMG_W;

    const int yu = (y0 > 0) ? y0 - 1 : 0;
    float4 tu = *(const float4*)(timg + (size_t)yu * IMG_W + x0);
    float4 tm = *(const float4*)(timg + (size_t)y0 * IMG_W + x0);
    float hu = 0.f, hm = 0.f;
    if (is_edge) {
        hu = timg[(size_t)yu * IMG_W + hcol];
        hm = timg[(size_t)y0 * IMG_W + hcol];
    }

    float sum = 0.0f;

    #pragma unroll 4
    for (int r = 0; r < RPB; r++) {
        const int y  = y0 + r;
        const int yd = (y < IMG_H - 1) ? y + 1 : y;
        const float4 td = *(const float4*)(timg + (size_t)yd * IMG_W + x0);
        const float4 pp = *(const float4*)(pimg + (size_t)y  * IMG_W + x0);
        float hd = 0.f;
        if (is_edge) hd = timg[(size_t)yd * IMG_W + hcol];

        // vertical (column) min/max of rows y-1,y,y+1
        float4 cmx, cmn;
        cmx.x = fmaxf(tm.x, fmaxf(tu.x, td.x));  cmn.x = fminf(tm.x, fminf(tu.x, td.x));
        cmx.y = fmaxf(tm.y, fmaxf(tu.y, td.y));  cmn.y = fminf(tm.y, fminf(tu.y, td.y));
        cmx.z = fmaxf(tm.z, fmaxf(tu.z, td.z));  cmn.z = fminf(tm.z, fminf(tu.z, td.z));
        cmx.w = fmaxf(tm.w, fmaxf(tu.w, td.w));  cmn.w = fminf(tm.w, fminf(tu.w, td.w));
        const float hmx = fmaxf(hm, fmaxf(hu, hd));
        const float hmn = fminf(hm, fminf(hu, hd));

        // neighbor columns across lanes
        float lmx = __shfl_up_sync  (0xFFFFFFFFu, cmx.w, 1);
        float lmn = __shfl_up_sync  (0xFFFFFFFFu, cmn.w, 1);
        float rmx = __shfl_down_sync(0xFFFFFFFFu, cmx.x, 1);
        float rmn = __shfl_down_sync(0xFFFFFFFFu, cmn.x, 1);
        if (lane == 0)  { lmx = hmx; lmn = hmn; }
        if (lane == 31) { rmx = hmx; rmn = hmn; }

        // horizontal 3-tap combine -> boundary flag -> weighted BCE
        float bx, bn, arg;
        bx = fmaxf(lmx,  fmaxf(cmx.x, cmx.y));
        bn = fminf(lmn,  fminf(cmn.x, cmn.y));
        arg = (tm.x > 0.5f) ? pp.x : (1.0f - pp.x);
        sum = fmaf((bx != bn) ? 3.0f : 1.0f, -__logf(arg), sum);

        bx = fmaxf(cmx.x, fmaxf(cmx.y, cmx.z));
        bn = fminf(cmn.x, fminf(cmn.y, cmn.z));
        arg = (tm.y > 0.5f) ? pp.y : (1.0f - pp.y);
        sum = fmaf((bx != bn) ? 3.0f : 1.0f, -__logf(arg), sum);

        bx = fmaxf(cmx.y, fmaxf(cmx.z, cmx.w));
        bn = fminf(cmn.y, fminf(cmn.z, cmn.w));
        arg = (tm.z > 0.5f) ? pp.z : (1.0f - pp.z);
        sum = fmaf((bx != bn) ? 3.0f : 1.0f, -__logf(arg), sum);

        bx = fmaxf(cmx.z, fmaxf(cmx.w, rmx));
        bn = fminf(cmn.z, fminf(cmn.w, rmn));
        arg = (tm.w > 0.5f) ? pp.w : (1.0f - pp.w);
        sum = fmaf((bx != bn) ? 3.0f : 1.0f, -__logf(arg), sum);

        tu = tm;  tm = td;
        hu = hm;  hm = hd;
    }

    // ---- block reduction (fp32) ----
    #pragma unroll
    for (int off = 16; off > 0; off >>= 1)
        sum += __shfl_xor_sync(0xFFFFFFFFu, sum, off);
    if (lane == 0) s_warp[wid] = sum;
    __syncthreads();

    if (tid == 0) {
        float v = 0.0f;
        #pragma unroll
        for (int i = 0; i < 8; i++) v += s_warp[i];
        g_partial[blockIdx.y * gridDim.x + blockIdx.x] = v;
        __threadfence();
        const unsigned done = atomicAdd(&g_count, 1u);
        s_last = (done == NBLK - 1);
    }
    __syncthreads();

    // ---- last block: final fp64 reduction, reset counter ----
    if (s_last) {
        __threadfence();
        double v = (double)g_partial[tid]
                 + (double)g_partial[tid + 256]
                 + (double)g_partial[tid + 512]
                 + (double)g_partial[tid + 768];
        #pragma unroll
        for (int off = 16; off > 0; off >>= 1)
            v += __shfl_xor_sync(0xFFFFFFFFu, v, off);
        if (lane == 0) s_dwarp[wid] = v;
        __syncthreads();
        if (tid == 0) {
            double t = 0.0;
            #pragma unroll
            for (int i = 0; i < 8; i++) t += s_dwarp[i];
            out[0] = (float)(t / NPIXD);
            g_count = 0;   // restore for next graph replay (deterministic)
        }
    }
}

extern "C" void kernel_launch(void* const* d_in, const int* in_sizes, int n_in,
                              void* d_out, int out_size)
{
    const float* pred   = (const float*)d_in[0];
    const float* target = (const float*)d_in[1];
    float* out = (float*)d_out;

    dim3 grid(GX, IMG_B);   // (32, 32) = 1024 blocks
    babce_kernel<<<grid, 256>>>(pred, target, out);
}